// round 9
// baseline (speedup 1.0000x reference)
#include <cuda_runtime.h>
#include <cstdint>

// Channel-group winner-take-all, group size 4, NCHW fp32.
// x: [B, C, H, W] = [32, 512, 56, 56].
//
// R9 (= R8 retry; previous round was a container infra failure):
// final-form candidate — measured-best structure from the session.
//  - one float4 group-position per thread (4 front-batched LDG.128 +
//    4 STG.128, ~30 regs, no loop, no cache hints)  [R1: 57.5us ncu]
//  - block=256 (57.5us) beat block=512 (58.0us), ILP=2 (58.8us),
//    persistent grid (62.2us)
//  - exact grid, dead bounds-guard removed; collapsed unsigned index math
//    (base = (b*NCG+cg) * GRP*plane4 + p, since channel groups are
//    consecutive in memory).
// DRAM-bound at ~6.2 TB/s (77% of 8 TB/s spec) — the mixed R/W stream
// ceiling; all compute/L1/L2 pipes have >2x headroom.

#define GB  32u
#define GC  512u
#define GHW (56u * 56u)          // 3136
#define GRP 4u
#define HW4 (GHW / 4u)           // 784 float4 chunks per plane
#define NCG (GC / GRP)           // 128 channel groups
#define NWORK (GB * NCG * HW4)   // 3,211,264 float4 group-positions

#define NTHREADS 256u
#define NBLOCKS  (NWORK / NTHREADS)   // 12544, exact

__global__ __launch_bounds__(NTHREADS) void cgm_wta_kernel(
    const float4* __restrict__ x, float4* __restrict__ out)
{
    unsigned work = blockIdx.x * NTHREADS + threadIdx.x;

    unsigned p  = work % HW4;
    unsigned t2 = work / HW4;            // t2 = b*NCG + cg
    const unsigned plane4 = GHW / 4u;
    unsigned base = t2 * (GRP * plane4) + p;

    float4 v0 = x[base];
    float4 v1 = x[base + plane4];
    float4 v2 = x[base + 2u * plane4];
    float4 v3 = x[base + 3u * plane4];

    float4 m;
    m.x = fmaxf(fmaxf(v0.x, v1.x), fmaxf(v2.x, v3.x));
    m.y = fmaxf(fmaxf(v0.y, v1.y), fmaxf(v2.y, v3.y));
    m.z = fmaxf(fmaxf(v0.z, v1.z), fmaxf(v2.z, v3.z));
    m.w = fmaxf(fmaxf(v0.w, v1.w), fmaxf(v2.w, v3.w));

    float4 o0, o1, o2, o3;
    o0.x = (v0.x == m.x) ? v0.x : 0.0f;
    o0.y = (v0.y == m.y) ? v0.y : 0.0f;
    o0.z = (v0.z == m.z) ? v0.z : 0.0f;
    o0.w = (v0.w == m.w) ? v0.w : 0.0f;

    o1.x = (v1.x == m.x) ? v1.x : 0.0f;
    o1.y = (v1.y == m.y) ? v1.y : 0.0f;
    o1.z = (v1.z == m.z) ? v1.z : 0.0f;
    o1.w = (v1.w == m.w) ? v1.w : 0.0f;

    o2.x = (v2.x == m.x) ? v2.x : 0.0f;
    o2.y = (v2.y == m.y) ? v2.y : 0.0f;
    o2.z = (v2.z == m.z) ? v2.z : 0.0f;
    o2.w = (v2.w == m.w) ? v2.w : 0.0f;

    o3.x = (v3.x == m.x) ? v3.x : 0.0f;
    o3.y = (v3.y == m.y) ? v3.y : 0.0f;
    o3.z = (v3.z == m.z) ? v3.z : 0.0f;
    o3.w = (v3.w == m.w) ? v3.w : 0.0f;

    out[base]               = o0;
    out[base + plane4]      = o1;
    out[base + 2u * plane4] = o2;
    out[base + 3u * plane4] = o3;
}

extern "C" void kernel_launch(void* const* d_in, const int* in_sizes, int n_in,
                              void* d_out, int out_size)
{
    const float4* x   = (const float4*)d_in[0];
    float4*       out = (float4*)d_out;
    cgm_wta_kernel<<<NBLOCKS, NTHREADS>>>(x, out);
}